// round 3
// baseline (speedup 1.0000x reference)
#include <cuda_runtime.h>
#include <cstdint>
#include <cstddef>

// Problem constants
#define BB 64      // batch
#define FF 2048    // nos_filters
#define PP 196     // num_pixels
#define TT 25      // caption length
#define EE 512     // embed dim
#define HH 512     // hidden
#define AA 512     // attention dim
#define VV 30000   // vocab

// ---------------- scratch (static device memory; no allocations) ----------------
#define OFF_IMGT   ((size_t)0)                         // 12544*2048
#define OFF_ATT1   (OFF_IMGT + (size_t)12544*2048)     // 12544*512
#define OFF_IMGE   (OFF_ATT1 + (size_t)12544*512)      // 12544*512
#define OFF_MEAN   (OFF_IMGE + (size_t)12544*512)      // 64*2048
#define OFF_HA     (OFF_MEAN + (size_t)64*2048)        // 64*512
#define OFF_HB     (OFF_HA   + (size_t)64*512)         // 64*512
#define OFF_ATT2   (OFF_HB   + (size_t)64*512)         // 64*512
#define OFF_E      (OFF_ATT2 + (size_t)64*512)         // 64*196
#define OFF_ALPHA  (OFF_E    + (size_t)64*196)         // 64*196
#define OFF_X      (OFF_ALPHA+ (size_t)64*196)         // 64*1024
#define OFF_GI     (OFF_X    + (size_t)64*1024)        // 64*1536
#define OFF_GH     (OFF_GI   + (size_t)64*1536)        // 64*1536
#define SCRATCH_FLOATS (OFF_GH + (size_t)64*1536)

__device__ float g_scratch[SCRATCH_FLOATS];
__device__ int   g_capidx[BB * TT];

// ---------------- caption index conversion (int32 vs int64 autodetect) ----------
__global__ void cap_convert(const unsigned* __restrict__ cap, int* __restrict__ capidx, int n) {
    int t = threadIdx.x;
    int bad = 0;
    // If the buffer is int64, the high (odd) 32-bit words of the first n words
    // are all zero (values in [0, 30000)). If int32, odd words are random
    // caption ids (nonzero w.p. ~1).  Only reads the first n words (always valid).
    for (int i = 2 * t + 1; i < n; i += 2 * blockDim.x) bad |= (cap[i] != 0u);
    int anybad = __syncthreads_or(bad);
    if (anybad) { // int32
        for (int i = t; i < n; i += blockDim.x) capidx[i] = (int)cap[i];
    } else {      // int64
        const unsigned long long* c64 = (const unsigned long long*)cap;
        for (int i = t; i < n; i += blockDim.x) capidx[i] = (int)c64[i];
    }
}

// ---------------- transpose: cnn [B,F,P] -> imgT [B*P, F] ------------------------
__global__ void transpose_k(const float* __restrict__ cnn, float* __restrict__ imgT) {
    __shared__ float tile[32][33];
    int b = blockIdx.z;
    int p0 = blockIdx.x * 32, f0 = blockIdx.y * 32;
    int tx = threadIdx.x, ty = threadIdx.y; // (32, 8)
#pragma unroll
    for (int i = 0; i < 4; i++) {
        int f = f0 + ty + i * 8, p = p0 + tx;
        tile[ty + i * 8][tx] = (p < PP) ? cnn[((size_t)b * FF + f) * PP + p] : 0.f;
    }
    __syncthreads();
#pragma unroll
    for (int i = 0; i < 4; i++) {
        int p = p0 + ty + i * 8, f = f0 + tx;
        if (p < PP) imgT[((size_t)b * PP + p) * FF + f] = tile[tx][ty + i * 8];
    }
}

// ---------------- mean over P: imgT -> meanfeat [B, F] ---------------------------
__global__ void mean_kernel(const float* __restrict__ imgT, float* __restrict__ meanf) {
    int b = blockIdx.x;
    for (int f = threadIdx.x; f < FF; f += blockDim.x) {
        float acc = 0.f;
        const float* base = imgT + (size_t)b * PP * FF + f;
        for (int p = 0; p < PP; p++) acc += base[(size_t)p * FF];
        meanf[(size_t)b * FF + f] = acc * (1.0f / (float)PP);
    }
}

// ---------------- generic tiled SGEMM: C[M,N] = A[M,K] @ op(B) + bias ------------
// TRANSB=false: B is [K,N] row-major (ldb = N-stride). TRANSB=true: B is [N,K] row-major.
#define BM 64
#define BN 64
#define BK 16

template <bool TRANSB>
__global__ void sgemm(const float* __restrict__ A, int lda,
                      const float* __restrict__ Bm, int ldb,
                      float* __restrict__ C, int ldc,
                      const float* __restrict__ bias,
                      int M, int N, int K) {
    __shared__ float As[BK][BM];
    __shared__ float Bs[BK][BN + 1];
    int bm = blockIdx.y, bn = blockIdx.x;
    int t = threadIdx.x;            // 256 threads
    int tx = t & 15, ty = t >> 4;   // 16x16
    int row0 = bm * BM, col0 = bn * BN;
    float acc[4][4] = {};
    for (int k0 = 0; k0 < K; k0 += BK) {
#pragma unroll
        for (int i = 0; i < 4; i++) {
            int idx = t + i * 256;
            int k = idx & 15, m = idx >> 4;
            int gr = row0 + m;
            As[k][m] = (gr < M) ? A[(size_t)gr * lda + (k0 + k)] : 0.f;
        }
#pragma unroll
        for (int i = 0; i < 4; i++) {
            int idx = t + i * 256;
            if (TRANSB) {
                int k = idx & 15, n = idx >> 4;
                int gc = col0 + n;
                Bs[k][n] = (gc < N) ? Bm[(size_t)gc * ldb + (k0 + k)] : 0.f;
            } else {
                int n = idx & 63, k = idx >> 6;
                int gc = col0 + n;
                Bs[k][n] = (gc < N) ? Bm[(size_t)(k0 + k) * ldb + gc] : 0.f;
            }
        }
        __syncthreads();
#pragma unroll
        for (int kk = 0; kk < BK; kk++) {
            float a[4], b[4];
#pragma unroll
            for (int i = 0; i < 4; i++) a[i] = As[kk][ty * 4 + i];
#pragma unroll
            for (int j = 0; j < 4; j++) b[j] = Bs[kk][tx * 4 + j];
#pragma unroll
            for (int i = 0; i < 4; i++)
#pragma unroll
                for (int j = 0; j < 4; j++) acc[i][j] += a[i] * b[j];
        }
        __syncthreads();
    }
#pragma unroll
    for (int i = 0; i < 4; i++) {
        int r = row0 + ty * 4 + i;
        if (r >= M) continue;
#pragma unroll
        for (int j = 0; j < 4; j++) {
            int c = col0 + tx * 4 + j;
            if (c < N) C[(size_t)r * ldc + c] = acc[i][j] + (bias ? bias[c] : 0.f);
        }
    }
}

// ---------------- attention score e[b,p] -----------------------------------------
__global__ void e_kernel(const float* __restrict__ att1, const float* __restrict__ att2,
                         const float* __restrict__ wfull, const float* __restrict__ bfull,
                         float* __restrict__ e) {
    int gw = (blockIdx.x * blockDim.x + threadIdx.x) >> 5;
    int lane = threadIdx.x & 31;
    if (gw >= BB * PP) return;
    int b = gw / PP;
    const float* a1 = att1 + (size_t)gw * AA;
    const float* a2 = att2 + (size_t)b * AA;
    float acc = 0.f;
    for (int a = lane; a < AA; a += 32) {
        float v = a1[a] + a2[a];
        v = (v >= 0.f) ? v : 0.2f * v;   // leaky(0.2)
        acc += v * wfull[a];
    }
#pragma unroll
    for (int o = 16; o; o >>= 1) acc += __shfl_down_sync(0xffffffffu, acc, o);
    if (lane == 0) e[gw] = acc + bfull[0];
}

// ---------------- softmax over P, also writes alphas output ----------------------
__global__ void softmax_kernel(const float* __restrict__ e, float* __restrict__ alpha,
                               float* __restrict__ out_alpha, int t) {
    int b = blockIdx.x;
    int tid = threadIdx.x; // 256
    __shared__ float red[256];
    float v = (tid < PP) ? e[b * PP + tid] : -3.0e38f;
    red[tid] = v;
    __syncthreads();
    for (int s = 128; s; s >>= 1) {
        if (tid < s) red[tid] = fmaxf(red[tid], red[tid + s]);
        __syncthreads();
    }
    float m = red[0];
    __syncthreads();
    float ex = (tid < PP) ? expf(v - m) : 0.f;
    red[tid] = ex;
    __syncthreads();
    for (int s = 128; s; s >>= 1) {
        if (tid < s) red[tid] += red[tid + s];
        __syncthreads();
    }
    float inv = 1.f / red[0];
    if (tid < PP) {
        float a = ex * inv;
        alpha[b * PP + tid] = a;
        out_alpha[(size_t)b * TT * PP + (size_t)t * PP + tid] = a;
    }
}

// ---------------- x = [emb(caption_t), alpha-weighted imgE + b_embed] ------------
__global__ void xemb_kernel(const int* __restrict__ capidx, const float* __restrict__ emb,
                            const float* __restrict__ alpha, const float* __restrict__ imgE,
                            const float* __restrict__ b_embed, float* __restrict__ x, int t) {
    int b = blockIdx.x, tid = threadIdx.x; // 512 threads
    __shared__ float sal[PP];
    if (tid < PP) sal[tid] = alpha[b * PP + tid];
    __syncthreads();
    int idx = capidx[b * TT + t];
    x[(size_t)b * 1024 + tid] = emb[(size_t)idx * EE + tid];
    float acc = b_embed[tid];
    const float* base = imgE + (size_t)b * PP * EE + tid;
#pragma unroll 4
    for (int p = 0; p < PP; p++) acc += sal[p] * base[(size_t)p * EE];
    x[(size_t)b * 1024 + EE + tid] = acc;
}

// ---------------- GRU gate fusion ------------------------------------------------
__global__ void gru_gate(const float* __restrict__ gi, const float* __restrict__ gh,
                         const float* __restrict__ hin, float* __restrict__ hout) {
    int i = blockIdx.x * blockDim.x + threadIdx.x;
    if (i >= BB * HH) return;
    int b = i >> 9, u = i & 511;
    const float* gib = gi + (size_t)b * 3 * HH;
    const float* ghb = gh + (size_t)b * 3 * HH;
    float r = 1.f / (1.f + expf(-(gib[u] + ghb[u])));
    float z = 1.f / (1.f + expf(-(gib[HH + u] + ghb[HH + u])));
    float n = tanhf(gib[2 * HH + u] + r * ghb[2 * HH + u]);
    hout[i] = (1.f - z) * n + z * hin[i];
}

// ---------------- launch ---------------------------------------------------------
extern "C" void kernel_launch(void* const* d_in, const int* in_sizes, int n_in,
                              void* d_out, int out_size) {
    const float*    cnn     = (const float*)d_in[0];
    const unsigned* cap     = (const unsigned*)d_in[1];
    // d_in[2]: caption_size (all == T, unused)
    const float* emb     = (const float*)d_in[3];
    const float* W_enc   = (const float*)d_in[4];
    const float* b_enc   = (const float*)d_in[5];
    const float* W_dec   = (const float*)d_in[6];
    const float* b_dec   = (const float*)d_in[7];
    const float* w_full  = (const float*)d_in[8];
    const float* b_full  = (const float*)d_in[9];
    const float* W_init  = (const float*)d_in[10];
    const float* b_init  = (const float*)d_in[11];
    const float* W_embed = (const float*)d_in[12];
    const float* b_embed = (const float*)d_in[13];
    const float* W_ih    = (const float*)d_in[14];
    const float* b_ih    = (const float*)d_in[15];
    const float* W_hh    = (const float*)d_in[16];
    const float* b_hh    = (const float*)d_in[17];
    const float* W_out   = (const float*)d_in[18];
    const float* b_out   = (const float*)d_in[19];

    float* out       = (float*)d_out;
    float* out_alpha = out + (size_t)TT * BB * VV;

    void* sp = nullptr;
    cudaGetSymbolAddress(&sp, g_scratch);
    float* S = (float*)sp;
    void* cp = nullptr;
    cudaGetSymbolAddress(&cp, g_capidx);
    int* capidx = (int*)cp;

    float* imgT  = S + OFF_IMGT;
    float* att1  = S + OFF_ATT1;
    float* imgE  = S + OFF_IMGE;
    float* meanf = S + OFF_MEAN;
    float* hA    = S + OFF_HA;
    float* hB    = S + OFF_HB;
    float* att2  = S + OFF_ATT2;
    float* eacts = S + OFF_E;
    float* alpha = S + OFF_ALPHA;
    float* xbuf  = S + OFF_X;
    float* gi    = S + OFF_GI;
    float* gh    = S + OFF_GH;

    // init
    cap_convert<<<1, 256>>>(cap, capidx, BB * TT);
    transpose_k<<<dim3(7, FF / 32, BB), dim3(32, 8)>>>(cnn, imgT);
    mean_kernel<<<BB, 512>>>(imgT, meanf);
    // h0 = meanfeat @ W_init + b_init
    sgemm<false><<<dim3(HH / 64, 1), 256>>>(meanf, FF, W_init, HH, hA, HH, b_init, BB, HH, FF);
    // att1 = imgT @ W_enc + b_enc  [12544, 512]
    sgemm<false><<<dim3(AA / 64, (BB * PP) / 64), 256>>>(imgT, FF, W_enc, AA, att1, AA, b_enc,
                                                         BB * PP, AA, FF);
    // imgE = imgT @ W_embed (no bias; bias applied in xemb)  [12544, 512]
    sgemm<false><<<dim3(EE / 64, (BB * PP) / 64), 256>>>(imgT, FF, W_embed, EE, imgE, EE, nullptr,
                                                         BB * PP, EE, FF);

    for (int t = 0; t < TT; t++) {
        float* hin  = (t & 1) ? hB : hA;
        float* hout = (t & 1) ? hA : hB;
        // att2 = h @ W_dec + b_dec
        sgemm<false><<<dim3(AA / 64, 1), 256>>>(hin, HH, W_dec, AA, att2, AA, b_dec, BB, AA, HH);
        e_kernel<<<(BB * PP * 32 + 255) / 256, 256>>>(att1, att2, w_full, b_full, eacts);
        softmax_kernel<<<BB, 256>>>(eacts, alpha, out_alpha, t);
        xemb_kernel<<<BB, 512>>>(capidx, emb, alpha, imgE, b_embed, xbuf, t);
        // gi = x @ W_ih^T + b_ih   [64, 1536]
        sgemm<true><<<dim3((3 * HH) / 64, 1), 256>>>(xbuf, 2 * EE, W_ih, 2 * EE, gi, 3 * HH, b_ih,
                                                     BB, 3 * HH, 2 * EE);
        // gh = h @ W_hh^T + b_hh   [64, 1536]
        sgemm<true><<<dim3((3 * HH) / 64, 1), 256>>>(hin, HH, W_hh, HH, gh, 3 * HH, b_hh,
                                                     BB, 3 * HH, HH);
        gru_gate<<<(BB * HH + 255) / 256, 256>>>(gi, gh, hin, hout);
        // op = h_new @ W_out + b_out  -> packed[t*B : (t+1)*B, :]
        sgemm<false><<<dim3((VV + 63) / 64, 1), 256>>>(hout, HH, W_out, VV,
                                                       out + (size_t)t * BB * VV, VV, b_out,
                                                       BB, VV, HH);
    }
}

// round 4
// speedup vs baseline: 1.0020x; 1.0020x over previous
#include <cuda_runtime.h>
#include <cstdint>
#include <cstddef>

// Problem constants
#define BB 64      // batch
#define FF 2048    // nos_filters
#define PP 196     // num_pixels
#define TT 25      // caption length
#define EE 512     // embed dim
#define HH 512     // hidden
#define AA 512     // attention dim
#define VV 30000   // vocab

// ---------------- scratch (static device memory; no allocations) ----------------
#define OFF_IMGT   ((size_t)0)                         // 12544*2048
#define OFF_ATT1   (OFF_IMGT + (size_t)12544*2048)     // 12544*512
#define OFF_IMGE   (OFF_ATT1 + (size_t)12544*512)      // 12544*512
#define OFF_MEAN   (OFF_IMGE + (size_t)12544*512)      // 64*2048
#define OFF_HA     (OFF_MEAN + (size_t)64*2048)        // 64*512
#define OFF_HB     (OFF_HA   + (size_t)64*512)         // 64*512
#define OFF_ATT2   (OFF_HB   + (size_t)64*512)         // 64*512
#define OFF_E      (OFF_ATT2 + (size_t)64*512)         // 64*196
#define OFF_ALPHA  (OFF_E    + (size_t)64*196)         // 64*196
#define OFF_X      (OFF_ALPHA+ (size_t)64*196)         // 64*1024
#define OFF_GI     (OFF_X    + (size_t)64*1024)        // 64*1536
#define OFF_GH     (OFF_GI   + (size_t)64*1536)        // 64*1536
#define SCRATCH_FLOATS (OFF_GH + (size_t)64*1536)

__device__ float g_scratch[SCRATCH_FLOATS];
__device__ int   g_capidx[BB * TT];

// ---------------- caption index conversion (int32 vs int64 autodetect) ----------
__global__ void cap_convert(const unsigned* __restrict__ cap, int* __restrict__ capidx, int n) {
    int t = threadIdx.x;
    int bad = 0;
    // If the buffer is int64, the high (odd) 32-bit words of the first n words
    // are all zero (values in [0, 30000)). If int32, odd words are random
    // caption ids (nonzero w.p. ~1).  Only reads the first n words (always valid).
    for (int i = 2 * t + 1; i < n; i += 2 * blockDim.x) bad |= (cap[i] != 0u);
    int anybad = __syncthreads_or(bad);
    if (anybad) { // int32
        for (int i = t; i < n; i += blockDim.x) capidx[i] = (int)cap[i];
    } else {      // int64
        const unsigned long long* c64 = (const unsigned long long*)cap;
        for (int i = t; i < n; i += blockDim.x) capidx[i] = (int)c64[i];
    }
}

// ---------------- transpose: cnn [B,F,P] -> imgT [B*P, F] ------------------------
__global__ void transpose_k(const float* __restrict__ cnn, float* __restrict__ imgT) {
    __shared__ float tile[32][33];
    int b = blockIdx.z;
    int p0 = blockIdx.x * 32, f0 = blockIdx.y * 32;
    int tx = threadIdx.x, ty = threadIdx.y; // (32, 8)
#pragma unroll
    for (int i = 0; i < 4; i++) {
        int f = f0 + ty + i * 8, p = p0 + tx;
        tile[ty + i * 8][tx] = (p < PP) ? cnn[((size_t)b * FF + f) * PP + p] : 0.f;
    }
    __syncthreads();
#pragma unroll
    for (int i = 0; i < 4; i++) {
        int p = p0 + ty + i * 8, f = f0 + tx;
        if (p < PP) imgT[((size_t)b * PP + p) * FF + f] = tile[tx][ty + i * 8];
    }
}

// ---------------- mean over P: imgT -> meanfeat [B, F] ---------------------------
__global__ void mean_kernel(const float* __restrict__ imgT, float* __restrict__ meanf) {
    int b = blockIdx.x;
    for (int f = threadIdx.x; f < FF; f += blockDim.x) {
        float acc = 0.f;
        const float* base = imgT + (size_t)b * PP * FF + f;
        for (int p = 0; p < PP; p++) acc += base[(size_t)p * FF];
        meanf[(size_t)b * FF + f] = acc * (1.0f / (float)PP);
    }
}

// ---------------- generic tiled SGEMM: C[M,N] = A[M,K] @ op(B) + bias ------------
// TRANSB=false: B is [K,N] row-major (ldb = N-stride). TRANSB=true: B is [N,K] row-major.
#define BM 64
#define BN 64
#define BK 16

template <bool TRANSB>
__global__ void sgemm(const float* __restrict__ A, int lda,
                      const float* __restrict__ Bm, int ldb,
                      float* __restrict__ C, int ldc,
                      const float* __restrict__ bias,
                      int M, int N, int K) {
    __shared__ float As[BK][BM];
    __shared__ float Bs[BK][BN + 1];
    int bm = blockIdx.y, bn = blockIdx.x;
    int t = threadIdx.x;            // 256 threads
    int tx = t & 15, ty = t >> 4;   // 16x16
    int row0 = bm * BM, col0 = bn * BN;
    float acc[4][4] = {};
    for (int k0 = 0; k0 < K; k0 += BK) {
#pragma unroll
        for (int i = 0; i < 4; i++) {
            int idx = t + i * 256;
            int k = idx & 15, m = idx >> 4;
            int gr = row0 + m;
            As[k][m] = (gr < M) ? A[(size_t)gr * lda + (k0 + k)] : 0.f;
        }
#pragma unroll
        for (int i = 0; i < 4; i++) {
            int idx = t + i * 256;
            if (TRANSB) {
                int k = idx & 15, n = idx >> 4;
                int gc = col0 + n;
                Bs[k][n] = (gc < N) ? Bm[(size_t)gc * ldb + (k0 + k)] : 0.f;
            } else {
                int n = idx & 63, k = idx >> 6;
                int gc = col0 + n;
                Bs[k][n] = (gc < N) ? Bm[(size_t)(k0 + k) * ldb + gc] : 0.f;
            }
        }
        __syncthreads();
#pragma unroll
        for (int kk = 0; kk < BK; kk++) {
            float a[4], b[4];
#pragma unroll
            for (int i = 0; i < 4; i++) a[i] = As[kk][ty * 4 + i];
#pragma unroll
            for (int j = 0; j < 4; j++) b[j] = Bs[kk][tx * 4 + j];
#pragma unroll
            for (int i = 0; i < 4; i++)
#pragma unroll
                for (int j = 0; j < 4; j++) acc[i][j] += a[i] * b[j];
        }
        __syncthreads();
    }
#pragma unroll
    for (int i = 0; i < 4; i++) {
        int r = row0 + ty * 4 + i;
        if (r >= M) continue;
#pragma unroll
        for (int j = 0; j < 4; j++) {
            int c = col0 + tx * 4 + j;
            if (c < N) C[(size_t)r * ldc + c] = acc[i][j] + (bias ? bias[c] : 0.f);
        }
    }
}

// ---------------- attention score e[b,p] -----------------------------------------
__global__ void e_kernel(const float* __restrict__ att1, const float* __restrict__ att2,
                         const float* __restrict__ wfull, const float* __restrict__ bfull,
                         float* __restrict__ e) {
    int gw = (blockIdx.x * blockDim.x + threadIdx.x) >> 5;
    int lane = threadIdx.x & 31;
    if (gw >= BB * PP) return;
    int b = gw / PP;
    const float* a1 = att1 + (size_t)gw * AA;
    const float* a2 = att2 + (size_t)b * AA;
    float acc = 0.f;
    for (int a = lane; a < AA; a += 32) {
        float v = a1[a] + a2[a];
        v = (v >= 0.f) ? v : 0.2f * v;   // leaky(0.2)
        acc += v * wfull[a];
    }
#pragma unroll
    for (int o = 16; o; o >>= 1) acc += __shfl_down_sync(0xffffffffu, acc, o);
    if (lane == 0) e[gw] = acc + bfull[0];
}

// ---------------- softmax over P, also writes alphas output ----------------------
__global__ void softmax_kernel(const float* __restrict__ e, float* __restrict__ alpha,
                               float* __restrict__ out_alpha, int t) {
    int b = blockIdx.x;
    int tid = threadIdx.x; // 256
    __shared__ float red[256];
    float v = (tid < PP) ? e[b * PP + tid] : -3.0e38f;
    red[tid] = v;
    __syncthreads();
    for (int s = 128; s; s >>= 1) {
        if (tid < s) red[tid] = fmaxf(red[tid], red[tid + s]);
        __syncthreads();
    }
    float m = red[0];
    __syncthreads();
    float ex = (tid < PP) ? expf(v - m) : 0.f;
    red[tid] = ex;
    __syncthreads();
    for (int s = 128; s; s >>= 1) {
        if (tid < s) red[tid] += red[tid + s];
        __syncthreads();
    }
    float inv = 1.f / red[0];
    if (tid < PP) {
        float a = ex * inv;
        alpha[b * PP + tid] = a;
        out_alpha[(size_t)b * TT * PP + (size_t)t * PP + tid] = a;
    }
}

// ---------------- x = [emb(caption_t), alpha-weighted imgE + b_embed] ------------
__global__ void xemb_kernel(const int* __restrict__ capidx, const float* __restrict__ emb,
                            const float* __restrict__ alpha, const float* __restrict__ imgE,
                            const float* __restrict__ b_embed, float* __restrict__ x, int t) {
    int b = blockIdx.x, tid = threadIdx.x; // 512 threads
    __shared__ float sal[PP];
    if (tid < PP) sal[tid] = alpha[b * PP + tid];
    __syncthreads();
    int idx = capidx[b * TT + t];
    x[(size_t)b * 1024 + tid] = emb[(size_t)idx * EE + tid];
    float acc = b_embed[tid];
    const float* base = imgE + (size_t)b * PP * EE + tid;
#pragma unroll 4
    for (int p = 0; p < PP; p++) acc += sal[p] * base[(size_t)p * EE];
    x[(size_t)b * 1024 + EE + tid] = acc;
}

// ---------------- GRU gate fusion ------------------------------------------------
__global__ void gru_gate(const float* __restrict__ gi, const float* __restrict__ gh,
                         const float* __restrict__ hin, float* __restrict__ hout) {
    int i = blockIdx.x * blockDim.x + threadIdx.x;
    if (i >= BB * HH) return;
    int b = i >> 9, u = i & 511;
    const float* gib = gi + (size_t)b * 3 * HH;
    const float* ghb = gh + (size_t)b * 3 * HH;
    float r = 1.f / (1.f + expf(-(gib[u] + ghb[u])));
    float z = 1.f / (1.f + expf(-(gib[HH + u] + ghb[HH + u])));
    float n = tanhf(gib[2 * HH + u] + r * ghb[2 * HH + u]);
    hout[i] = (1.f - z) * n + z * hin[i];
}

// ---------------- launch ---------------------------------------------------------
extern "C" void kernel_launch(void* const* d_in, const int* in_sizes, int n_in,
                              void* d_out, int out_size) {
    const float*    cnn     = (const float*)d_in[0];
    const unsigned* cap     = (const unsigned*)d_in[1];
    // d_in[2]: caption_size (all == T, unused)
    const float* emb     = (const float*)d_in[3];
    const float* W_enc   = (const float*)d_in[4];
    const float* b_enc   = (const float*)d_in[5];
    const float* W_dec   = (const float*)d_in[6];
    const float* b_dec   = (const float*)d_in[7];
    const float* w_full  = (const float*)d_in[8];
    const float* b_full  = (const float*)d_in[9];
    const float* W_init  = (const float*)d_in[10];
    const float* b_init  = (const float*)d_in[11];
    const float* W_embed = (const float*)d_in[12];
    const float* b_embed = (const float*)d_in[13];
    const float* W_ih    = (const float*)d_in[14];
    const float* b_ih    = (const float*)d_in[15];
    const float* W_hh    = (const float*)d_in[16];
    const float* b_hh    = (const float*)d_in[17];
    const float* W_out   = (const float*)d_in[18];
    const float* b_out   = (const float*)d_in[19];

    float* out       = (float*)d_out;
    float* out_alpha = out + (size_t)TT * BB * VV;

    void* sp = nullptr;
    cudaGetSymbolAddress(&sp, g_scratch);
    float* S = (float*)sp;
    void* cp = nullptr;
    cudaGetSymbolAddress(&cp, g_capidx);
    int* capidx = (int*)cp;

    float* imgT  = S + OFF_IMGT;
    float* att1  = S + OFF_ATT1;
    float* imgE  = S + OFF_IMGE;
    float* meanf = S + OFF_MEAN;
    float* hA    = S + OFF_HA;
    float* hB    = S + OFF_HB;
    float* att2  = S + OFF_ATT2;
    float* eacts = S + OFF_E;
    float* alpha = S + OFF_ALPHA;
    float* xbuf  = S + OFF_X;
    float* gi    = S + OFF_GI;
    float* gh    = S + OFF_GH;

    // init
    cap_convert<<<1, 256>>>(cap, capidx, BB * TT);
    transpose_k<<<dim3(7, FF / 32, BB), dim3(32, 8)>>>(cnn, imgT);
    mean_kernel<<<BB, 512>>>(imgT, meanf);
    // h0 = meanfeat @ W_init + b_init
    sgemm<false><<<dim3(HH / 64, 1), 256>>>(meanf, FF, W_init, HH, hA, HH, b_init, BB, HH, FF);
    // att1 = imgT @ W_enc + b_enc  [12544, 512]
    sgemm<false><<<dim3(AA / 64, (BB * PP) / 64), 256>>>(imgT, FF, W_enc, AA, att1, AA, b_enc,
                                                         BB * PP, AA, FF);
    // imgE = imgT @ W_embed (no bias; bias applied in xemb)  [12544, 512]
    sgemm<false><<<dim3(EE / 64, (BB * PP) / 64), 256>>>(imgT, FF, W_embed, EE, imgE, EE, nullptr,
                                                         BB * PP, EE, FF);

    for (int t = 0; t < TT; t++) {
        float* hin  = (t & 1) ? hB : hA;
        float* hout = (t & 1) ? hA : hB;
        // att2 = h @ W_dec + b_dec
        sgemm<false><<<dim3(AA / 64, 1), 256>>>(hin, HH, W_dec, AA, att2, AA, b_dec, BB, AA, HH);
        e_kernel<<<(BB * PP * 32 + 255) / 256, 256>>>(att1, att2, w_full, b_full, eacts);
        softmax_kernel<<<BB, 256>>>(eacts, alpha, out_alpha, t);
        xemb_kernel<<<BB, 512>>>(capidx, emb, alpha, imgE, b_embed, xbuf, t);
        // gi = x @ W_ih^T + b_ih   [64, 1536]
        sgemm<true><<<dim3((3 * HH) / 64, 1), 256>>>(xbuf, 2 * EE, W_ih, 2 * EE, gi, 3 * HH, b_ih,
                                                     BB, 3 * HH, 2 * EE);
        // gh = h @ W_hh^T + b_hh   [64, 1536]
        sgemm<true><<<dim3((3 * HH) / 64, 1), 256>>>(hin, HH, W_hh, HH, gh, 3 * HH, b_hh,
                                                     BB, 3 * HH, HH);
        gru_gate<<<(BB * HH + 255) / 256, 256>>>(gi, gh, hin, hout);
        // op = h_new @ W_out + b_out  -> packed[t*B : (t+1)*B, :]
        sgemm<false><<<dim3((VV + 63) / 64, 1), 256>>>(hout, HH, W_out, VV,
                                                       out + (size_t)t * BB * VV, VV, b_out,
                                                       BB, VV, HH);
    }
}